// round 13
// baseline (speedup 1.0000x reference)
#include <cuda_runtime.h>
#include <math.h>

#define L      2304
#define DM     128
#define DI     256
#define DS     16
#define DTR    8
#define NPROJ  40   // DTR + 2*DS
#define NDEPTH 8
#define CHK1   8    // chunk for mid/scan1
#define NC1    (L/CHK1)   // 288
#define CHKO   16   // chunk for fused_out
#define NCO    (L/CHKO)   // 144
#define NSEQ   (DI*DS)    // 4096
#define SEQT   32

typedef unsigned long long u64;

__device__ __forceinline__ u64 pack2(float lo, float hi) {
    u64 r;
    asm("mov.b64 %0, {%1, %2};" : "=l"(r)
        : "r"(__float_as_uint(lo)), "r"(__float_as_uint(hi)));
    return r;
}
__device__ __forceinline__ u64 fma2(u64 a, u64 b, u64 c) {
    u64 d;
    asm("fma.rn.f32x2 %0, %1, %2, %3;" : "=l"(d) : "l"(a), "l"(b), "l"(c));
    return d;
}
__device__ __forceinline__ void unpack2(u64 v, float& lo, float& hi) {
    unsigned a, b;
    asm("mov.b64 {%0, %1}, %2;" : "=r"(a), "=r"(b) : "l"(v));
    lo = __uint_as_float(a); hi = __uint_as_float(b);
}

// ---------------- scratch (device globals; no allocations) ----------------
__device__ float g_seq[L*DM];
__device__ float g_xz [L*2*DI];
__device__ float g_xc [L*DI];
__device__ float g_dbl[L*NPROJ];
__device__ float g_dt [L*DI];
__device__ float g_chA[NC1*NSEQ];   // [chunk8][s*DI + d]
__device__ float g_chB[NC1*NSEQ];
__device__ float g_h0 [NCO*NSEQ];   // h0 per 16-row block

// ======= in-proj GEMM: xz[L,512] = A[L,128] @ Wi[128,512] =======
// BM=32, BN=128, BK=16; 128 threads, 4x8 per thread via packed f32x2 FMA.
__global__ void __launch_bounds__(128) gemm_in_k(const float* __restrict__ A,
                                                 const float* __restrict__ B,
                                                 float* __restrict__ C,
                                                 int transA) {
    __shared__ float As[16][36];
    __shared__ float Bs[16][128];
    int t = threadIdx.x;
    int tr = t >> 4, tc = t & 15;
    int row0 = blockIdx.y * 32, col0 = blockIdx.x * 128;
    u64 acc[4][4];
    #pragma unroll
    for (int i = 0; i < 4; i++)
        #pragma unroll
        for (int j = 0; j < 4; j++) acc[i][j] = 0ull;

    for (int k0 = 0; k0 < DM; k0 += 16) {
        if (transA) {
            int k = t >> 3, m4 = t & 7;
            float4 v = *(const float4*)&A[(k0 + k) * L + row0 + m4 * 4];
            *(float4*)&As[k][m4 * 4] = v;
        } else {
            int m = t >> 2, kq = t & 3;
            float4 v = *(const float4*)&A[(row0 + m) * DM + k0 + kq * 4];
            As[kq*4+0][m] = v.x; As[kq*4+1][m] = v.y;
            As[kq*4+2][m] = v.z; As[kq*4+3][m] = v.w;
        }
        #pragma unroll
        for (int i = 0; i < 4; i++) {
            int li = t + i * 128;
            int k = li >> 5, c4 = li & 31;
            *(float4*)&Bs[k][c4 * 4] = *(const float4*)&B[(k0 + k) * 512 + col0 + c4 * 4];
        }
        __syncthreads();
        #pragma unroll
        for (int k = 0; k < 16; k++) {
            float a[4];
            *(float4*)&a[0] = *(float4*)&As[k][tr * 4];
            float4 b0 = *(float4*)&Bs[k][tc * 8];
            float4 b1 = *(float4*)&Bs[k][tc * 8 + 4];
            u64 bb[4] = {pack2(b0.x, b0.y), pack2(b0.z, b0.w),
                         pack2(b1.x, b1.y), pack2(b1.z, b1.w)};
            #pragma unroll
            for (int i = 0; i < 4; i++) {
                u64 aa = pack2(a[i], a[i]);
                #pragma unroll
                for (int j = 0; j < 4; j++)
                    acc[i][j] = fma2(aa, bb[j], acc[i][j]);
            }
        }
        __syncthreads();
    }
    #pragma unroll
    for (int i = 0; i < 4; i++) {
        int r = row0 + tr * 4 + i;
        float4 v0, v1;
        unpack2(acc[i][0], v0.x, v0.y); unpack2(acc[i][1], v0.z, v0.w);
        unpack2(acc[i][2], v1.x, v1.y); unpack2(acc[i][3], v1.z, v1.w);
        *(float4*)&C[r * 512 + col0 + tc * 8]     = v0;
        *(float4*)&C[r * 512 + col0 + tc * 8 + 4] = v1;
    }
}

// ======= fused: conv+SiLU -> xproj -> dt(softplus) -> scan pass 1 =======
// CHK1=8 rows per block, 288 blocks, 2 blocks/SM.
__global__ void __launch_bounds__(256, 2) fused_mid_k(
    const float* __restrict__ cw, const float* __restrict__ cb,
    const float* __restrict__ Wx, const float* __restrict__ Wdt,
    const float* __restrict__ bdt, const float* __restrict__ Alog)
{
    __shared__ float xc_s[CHK1 * 257];
    __shared__ float Wx_s[128 * 48];
    __shared__ float dbl_s[CHK1 * NPROJ];
    int t  = threadIdx.x;
    int l0 = blockIdx.x * CHK1;

    float xcr[CHK1], dtr[CHK1];

    // ---- conv + SiLU: batched loads then compute ----
    {
        int d = t;
        float v[CHK1 + 3];
        #pragma unroll
        for (int i = 0; i < CHK1 + 3; i++) {
            int l = l0 + i - 3;
            v[i] = (l >= 0) ? g_xz[l*512 + d] : 0.f;
        }
        float c0 = cw[d*4+0], c1 = cw[d*4+1], c2 = cw[d*4+2], c3 = cw[d*4+3];
        float bb = cb[d];
        #pragma unroll
        for (int r = 0; r < CHK1; r++) {
            float acc = bb + v[r]*c0 + v[r+1]*c1 + v[r+2]*c2 + v[r+3]*c3;
            acc = acc / (1.f + __expf(-acc));
            xcr[r] = acc;
            xc_s[r*257 + d] = acc;
            g_xc[(l0+r)*DI + d] = acc;
        }
    }

    // ---- xproj: dbl[8,40] = xc[8,256] @ Wx[256,40]; 32 groups x 2 cols ----
    int row = t & 7, g = t >> 3;
    int c0i = g * 2;
    float a0 = 0.f, a1 = 0.f;
    for (int p = 0; p < 2; p++) {
        __syncthreads();
        for (int i = t; i < 128 * NPROJ; i += 256) {
            int k = i / NPROJ, c = i % NPROJ;
            Wx_s[k*48 + c] = Wx[(p*128 + k) * NPROJ + c];
        }
        __syncthreads();
        const float* xr = xc_s + row*257 + p*128;
        if (c0i < NPROJ) {
            #pragma unroll 4
            for (int k = 0; k < 128; k++) {
                float xv = xr[k];
                a0 += xv * Wx_s[k*48 + c0i];
                a1 += xv * Wx_s[k*48 + c0i + 1];
            }
        }
    }
    if (c0i     < NPROJ) { dbl_s[row*NPROJ + c0i]     = a0; g_dbl[(l0+row)*NPROJ + c0i]     = a0; }
    if (c0i + 1 < NPROJ) { dbl_s[row*NPROJ + c0i + 1] = a1; g_dbl[(l0+row)*NPROJ + c0i + 1] = a1; }
    __syncthreads();

    // ---- dt = softplus ----
    {
        int d = t;
        float w[DTR];
        #pragma unroll
        for (int k = 0; k < DTR; k++) w[k] = Wdt[k*DI + d];
        float bb = bdt[d];
        #pragma unroll
        for (int r = 0; r < CHK1; r++) {
            float acc = bb;
            #pragma unroll
            for (int k = 0; k < DTR; k++) acc += dbl_s[r*NPROJ + k] * w[k];
            float sp = (acc > 20.f) ? acc : log1pf(__expf(acc));
            dtr[r] = sp;
            g_dt[(l0+r)*DI + d] = sp;
        }
    }

    // ---- scan pass 1 (8 steps) ----
    {
        int d = t;
        float Arow[DS], a[DS], b[DS];
        #pragma unroll
        for (int s = 0; s < DS; s++) {
            Arow[s] = -__expf(Alog[d*DS + s]);
            a[s] = 1.f; b[s] = 0.f;
        }
        #pragma unroll 4
        for (int r = 0; r < CHK1; r++) {
            float dt = dtr[r], dtxc = dt * xcr[r];
            #pragma unroll
            for (int s = 0; s < DS; s++) {
                float dA = __expf(dt * Arow[s]);
                b[s] = dA * b[s] + dtxc * dbl_s[r*NPROJ + DTR + s];
                a[s] *= dA;
            }
        }
        int base = blockIdx.x * NSEQ + d;
        #pragma unroll
        for (int s = 0; s < DS; s++) {
            g_chA[base + s*DI] = a[s];
            g_chB[base + s*DI] = b[s];
        }
    }
}

// ======= scan pass 2: pair-combine at load + 144-row Kogge-Stone =======
// 128 blocks x 512 threads; static smem 2 x [144][33] (38KB).
// Combines 288 8-row chunks into 144 16-row pairs in registers, then KS.
__global__ void __launch_bounds__(512) scan2_k() {
    __shared__ float A_s[NCO][SEQT + 1];
    __shared__ float B_s[NCO][SEQT + 1];
    int t = threadIdx.x;
    int w = t >> 5, lane = t & 31;
    int seq0 = blockIdx.x * SEQT;

    {   // batched staging with pair combine: 9 pairs (18 raw chunks) per warp
        float a0[9], a1[9], b0[9], b1[9];
        #pragma unroll
        for (int i = 0; i < 9; i++) {
            int p = w + i * 16;          // pair index 0..143
            int idx0 = (2*p)     * NSEQ + seq0 + lane;
            int idx1 = (2*p + 1) * NSEQ + seq0 + lane;
            a0[i] = g_chA[idx0]; a1[i] = g_chA[idx1];
            b0[i] = g_chB[idx0]; b1[i] = g_chB[idx1];
        }
        #pragma unroll
        for (int i = 0; i < 9; i++) {
            int p = w + i * 16;
            A_s[p][lane] = a1[i] * a0[i];
            B_s[p][lane] = a1[i] * b0[i] + b1[i];
        }
    }
    __syncthreads();

    // each warp scans 2 columns over 144 pairs = 5 rounds
    #pragma unroll
    for (int q = 0; q < 2; q++) {
        int col = w * 2 + q;
        float ra[5], rb[5];
        #pragma unroll
        for (int k = 0; k < 5; k++) {
            int c = k * 32 + lane;
            if (c < NCO) { ra[k] = A_s[c][col]; rb[k] = B_s[c][col]; }
            else         { ra[k] = 1.f;         rb[k] = 0.f; }
        }
        #pragma unroll
        for (int off = 1; off < 32; off <<= 1) {
            float pa[5], pb[5];
            #pragma unroll
            for (int k = 0; k < 5; k++) {
                pa[k] = __shfl_up_sync(0xffffffffu, ra[k], off);
                pb[k] = __shfl_up_sync(0xffffffffu, rb[k], off);
            }
            #pragma unroll
            for (int k = 0; k < 5; k++)
                if (lane >= off) { rb[k] = ra[k] * pb[k] + rb[k]; ra[k] *= pa[k]; }
        }
        float ea[5], eb[5];
        #pragma unroll
        for (int k = 0; k < 5; k++) {
            ea[k] = __shfl_up_sync(0xffffffffu, ra[k], 1);
            eb[k] = __shfl_up_sync(0xffffffffu, rb[k], 1);
            if (lane == 0) { ea[k] = 1.f; eb[k] = 0.f; }
        }
        float H = 0.f;
        #pragma unroll
        for (int k = 0; k < 5; k++) {
            int c = k * 32 + lane;
            float h0 = ea[k] * H + eb[k];
            if (c < NCO) A_s[c][col] = h0;
            float ta = __shfl_sync(0xffffffffu, ra[k], 31);
            float tb = __shfl_sync(0xffffffffu, rb[k], 31);
            H = ta * H + tb;
        }
    }
    __syncthreads();

    #pragma unroll
    for (int i = 0; i < 9; i++) {
        int p = w + i * 16;
        g_h0[p * NSEQ + seq0 + lane] = A_s[p][lane];
    }
}

// ======= fused: scan pass 3 + gate -> out-proj GEMM -> RMSNorm =======
// CHKO=16 rows, 144 blocks; Wo tiles register-prefetched.
__global__ void __launch_bounds__(256) fused_out_k(
    const float* __restrict__ Alog, const float* __restrict__ Dp,
    const float* __restrict__ Wo, const float* __restrict__ rw,
    float* __restrict__ outp)
{
    __shared__ float y_s[CHKO * DI];
    __shared__ float Wo_s[32 * DM];
    __shared__ float Bs_s[CHKO][DS];
    __shared__ float Cs_s[CHKO][DS];
    int t  = threadIdx.x;
    int l0 = blockIdx.x * CHKO;

    {
        int r = t >> 4, s = t & 15;
        int base = (l0 + r) * NPROJ + DTR;
        Bs_s[r][s] = g_dbl[base + s];
        Cs_s[r][s] = g_dbl[base + DS + s];
    }

    // ---- phase A: scan with init state, C-contract, D-skip, z-gate ----
    {
        int d = t;
        float dtv[CHKO], xcv[CHKO], zv[CHKO], h[DS], Arow[DS];
        #pragma unroll
        for (int r = 0; r < CHKO; r++) {
            int l = l0 + r;
            dtv[r] = g_dt[l*DI + d];
            xcv[r] = g_xc[l*DI + d];
            zv[r]  = g_xz[l*512 + DI + d];
        }
        int hb = blockIdx.x * NSEQ + d;
        #pragma unroll
        for (int s = 0; s < DS; s++) {
            Arow[s] = -__expf(Alog[d*DS + s]);
            h[s] = g_h0[hb + s*DI];
        }
        float Dd = Dp[d];
        __syncthreads();   // Bs_s/Cs_s ready
        #pragma unroll 4
        for (int r = 0; r < CHKO; r++) {
            float dt = dtv[r], xc = xcv[r];
            float dtxc = dt * xc;
            float y = Dd * xc;
            #pragma unroll
            for (int s = 0; s < DS; s++) {
                float dA = __expf(dt * Arow[s]);
                h[s] = dA * h[s] + dtxc * Bs_s[r][s];
                y += h[s] * Cs_s[r][s];
            }
            float z = zv[r];
            y *= z / (1.f + __expf(-z));
            y_s[r*DI + d] = y;
        }
    }

    // ---- phase B: out[16,128] = y[16,256] @ Wo[256,128] + RMSNorm (f32x2) ----
    int w = t >> 5, lane = t & 31;
    int r0 = 2*w, r1 = 2*w + 1;
    int cb = lane * 4;
    u64 acc0[2] = {0ull, 0ull}, acc1[2] = {0ull, 0ull};

    // prefetch tile 0 into registers
    float4 pf[4];
    #pragma unroll
    for (int i = 0; i < 4; i++) {
        int idx = t + 256*i;
        int kk = idx >> 5, c4 = idx & 31;
        pf[i] = ((const float4*)(Wo + kk*DM))[c4];
    }
    for (int k0 = 0; k0 < DI; k0 += 32) {
        __syncthreads();
        #pragma unroll
        for (int i = 0; i < 4; i++) {
            int idx = t + 256*i;
            int kk = idx >> 5, c4 = idx & 31;
            ((float4*)Wo_s)[kk*32 + c4] = pf[i];
        }
        __syncthreads();
        if (k0 + 32 < DI) {
            #pragma unroll
            for (int i = 0; i < 4; i++) {
                int idx = t + 256*i;
                int kk = idx >> 5, c4 = idx & 31;
                pf[i] = ((const float4*)(Wo + (k0 + 32 + kk)*DM))[c4];
            }
        }
        #pragma unroll
        for (int kk = 0; kk < 32; kk += 4) {
            float4 y0 = *(const float4*)&y_s[r0*DI + k0 + kk];
            float4 y1 = *(const float4*)&y_s[r1*DI + k0 + kk];
            float ya0[4] = {y0.x, y0.y, y0.z, y0.w};
            float ya1[4] = {y1.x, y1.y, y1.z, y1.w};
            #pragma unroll
            for (int i = 0; i < 4; i++) {
                float4 wv = *(const float4*)&Wo_s[(kk+i)*DM + cb];
                u64 w01 = pack2(wv.x, wv.y), w23 = pack2(wv.z, wv.w);
                u64 a0p = pack2(ya0[i], ya0[i]);
                u64 a1p = pack2(ya1[i], ya1[i]);
                acc0[0] = fma2(a0p, w01, acc0[0]);
                acc0[1] = fma2(a0p, w23, acc0[1]);
                acc1[0] = fma2(a1p, w01, acc1[0]);
                acc1[1] = fma2(a1p, w23, acc1[1]);
            }
        }
    }
    float o0v[4], o1v[4];
    unpack2(acc0[0], o0v[0], o0v[1]); unpack2(acc0[1], o0v[2], o0v[3]);
    unpack2(acc1[0], o1v[0], o1v[1]); unpack2(acc1[1], o1v[2], o1v[3]);
    float ss0 = o0v[0]*o0v[0] + o0v[1]*o0v[1] + o0v[2]*o0v[2] + o0v[3]*o0v[3];
    float ss1 = o1v[0]*o1v[0] + o1v[1]*o1v[1] + o1v[2]*o1v[2] + o1v[3]*o1v[3];
    #pragma unroll
    for (int o = 16; o > 0; o >>= 1) {
        ss0 += __shfl_xor_sync(0xffffffffu, ss0, o);
        ss1 += __shfl_xor_sync(0xffffffffu, ss1, o);
    }
    float sc0 = rsqrtf(ss0 * (1.f/DM) + 1e-5f);
    float sc1 = rsqrtf(ss1 * (1.f/DM) + 1e-5f);
    float4 rwv = *(const float4*)&rw[cb];
    float rws[4] = {rwv.x, rwv.y, rwv.z, rwv.w};
    if (outp) {
        #pragma unroll
        for (int j = 0; j < 4; j++) {
            outp[(cb + j) * L + l0 + r0] = o0v[j] * sc0 * rws[j];
            outp[(cb + j) * L + l0 + r1] = o1v[j] * sc1 * rws[j];
        }
    } else {
        float4 o0, o1;
        o0.x = o0v[0]*sc0*rws[0]; o0.y = o0v[1]*sc0*rws[1];
        o0.z = o0v[2]*sc0*rws[2]; o0.w = o0v[3]*sc0*rws[3];
        o1.x = o1v[0]*sc1*rws[0]; o1.y = o1v[1]*sc1*rws[1];
        o1.z = o1v[2]*sc1*rws[2]; o1.w = o1v[3]*sc1*rws[3];
        *(float4*)&g_seq[(l0 + r0)*DM + cb] = o0;
        *(float4*)&g_seq[(l0 + r1)*DM + cb] = o1;
    }
}

// ---------------- launch ----------------
extern "C" void kernel_launch(void* const* d_in, const int* in_sizes, int n_in,
                              void* d_out, int out_size) {
    const float* x      = (const float*)d_in[0];
    const float* W_in   = (const float*)d_in[1];
    const float* conv_w = (const float*)d_in[2];
    const float* conv_b = (const float*)d_in[3];
    const float* W_xp   = (const float*)d_in[4];
    const float* W_dt   = (const float*)d_in[5];
    const float* b_dt   = (const float*)d_in[6];
    const float* A_log  = (const float*)d_in[7];
    const float* D_skip = (const float*)d_in[8];
    const float* W_out  = (const float*)d_in[9];
    const float* rms_w  = (const float*)d_in[10];
    float* out = (float*)d_out;

    float *p_seq, *p_xz;
    cudaGetSymbolAddress((void**)&p_seq, g_seq);
    cudaGetSymbolAddress((void**)&p_xz,  g_xz);

    for (int l = 0; l < NDEPTH; l++) {
        const float* Wi  = W_in   + (size_t)l * DM * 2 * DI;
        const float* cw  = conv_w + (size_t)l * DI * 4;
        const float* cb  = conv_b + (size_t)l * DI;
        const float* Wx  = W_xp   + (size_t)l * DI * NPROJ;
        const float* Wd  = W_dt   + (size_t)l * DTR * DI;
        const float* bd  = b_dt   + (size_t)l * DI;
        const float* Al  = A_log  + (size_t)l * DI * DS;
        const float* Dpp = D_skip + (size_t)l * DI;
        const float* Wo  = W_out  + (size_t)l * DI * DM;
        const float* rw  = rms_w  + (size_t)l * DM;

        gemm_in_k<<<dim3(4, 72), 128>>>(l == 0 ? x : p_seq, Wi, p_xz, l == 0 ? 1 : 0);
        fused_mid_k<<<NC1, 256>>>(cw, cb, Wx, Wd, bd, Al);
        scan2_k<<<NSEQ / SEQT, 512>>>();
        fused_out_k<<<NCO, 256>>>(Al, Dpp, Wo, rw, (l == NDEPTH - 1) ? out : nullptr);
    }
}